// round 9
// baseline (speedup 1.0000x reference)
#include <cuda_runtime.h>

// GCBFSafetyLayer — final: copy-engine graph node (confirmation run).
//
// Algebraic reduction (verified rel_err = 0.0, 9/9 rounds):
//   L_g_h = dh_dx @ g == 0 identically — dh_dx's nonzero state columns
//   (position jacobian, cols 0..1) hit only g's zero rows (0..1); g's I/MASS
//   rows (2..3) hit dh_dx's zero columns (2..3). In project(),
//   an = ||a||^2 = 0 fails the (an > 1e-6) gate for every constraint, every
//   iteration -> u never changes -> safe_action == raw_action BIT-EXACT.
// Work = copy d_in[3] (B*N*P = 65536 f32 = 256 KB) to d_out.
//
// Measurement history (harness us): SM kernel 128x128 float4: 4.58, 4.61,
// 5.76, 5.63 | CE memcpy node: 4.61. Both paths sit at the same ~4.6us
// launch/replay floor; CE ties best-ever with the simplest possible graph
// (one memcpy node, no SM launch, no kernel code). ncu shows no profile for
// CE nodes — expected, there is no SM kernel to profile.

extern "C" void kernel_launch(void* const* d_in, const int* in_sizes, int n_in,
                              void* d_out, int out_size) {
    // inputs: [0] positions, [1] velocities, [2] obstacles, [3] raw_action
    cudaMemcpyAsync(d_out, d_in[3], (size_t)in_sizes[3] * sizeof(float),
                    cudaMemcpyDeviceToDevice, 0);
}

// round 10
// speedup vs baseline: 1.0395x; 1.0395x over previous
#include <cuda_runtime.h>

// GCBFSafetyLayer — FINAL (frozen; R2/R4 measured-best configuration).
//
// Algebraic reduction (verified rel_err = 0.0, 10/10 rounds):
//   L_g_h = dh_dx @ g == 0 identically. dh_dx = [jac_pos | 0] puts the
//   position Jacobian in state columns 0..1; g = [0 ; I/MASS] has nonzero
//   rows only at 2..3. Their product vanishes. In project(), every constraint
//   row a = 0, so an = ||a||^2 = 0 fails the (an > 1e-6) gate on every inner
//   iteration of every outer iteration -> u is never modified ->
//   safe_action == raw_action BIT-EXACT.
// Remaining work: copy d_in[3] (B*N*P = 65536 f32 = 16384 float4) to d_out.
//
// Ten-round measurement summary (harness us):
//   SM kernel 128x128 float4/thread: 4.58, 4.61, 5.76, 5.63  (ncu 4.13-4.48)
//   CE memcpyAsync node:             4.61, 5.89              (no ncu view)
//   Rejected: 64x256 bounds-checked (6.43), 2 ld/thread @64 CTAs (4.93),
//             __stcs streaming stores (5.41).
// Both node types sample the same ~4.6us graph-replay floor; the duration is
// launch overhead (T_ovh ~5000 cyc + one DRAM round trip), DRAM at 0.8% of
// peak by construction. SM kernel chosen for ncu observability + best
// kernel-duration sample (4.13us). Further changes would be fitting noise.

__global__ __launch_bounds__(128, 1)
void gcbf_copy_kernel(const float4* __restrict__ src, float4* __restrict__ dst) {
    int i = blockIdx.x * 128 + threadIdx.x;
    dst[i] = src[i];
}

extern "C" void kernel_launch(void* const* d_in, const int* in_sizes, int n_in,
                              void* d_out, int out_size) {
    // inputs: [0] positions, [1] velocities, [2] obstacles, [3] raw_action
    gcbf_copy_kernel<<<128, 128>>>((const float4*)d_in[3], (float4*)d_out);
}

// round 11
// speedup vs baseline: 1.0514x; 1.0114x over previous
#include <cuda_runtime.h>

// GCBFSafetyLayer — FINAL (frozen; R2/R4 measured-best configuration).
//
// Algebraic reduction (verified rel_err = 0.0, 11/11 rounds):
//   L_g_h = dh_dx @ g == 0 identically. dh_dx = [jac_pos | 0] puts the
//   position Jacobian in state columns 0..1; g = [0 ; I/MASS] has nonzero
//   rows only at 2..3. Their product vanishes. In project(), every constraint
//   row a = 0, so an = ||a||^2 = 0 fails the (an > 1e-6) gate on every inner
//   iteration of every outer iteration -> u is never modified ->
//   safe_action == raw_action BIT-EXACT.
// Remaining work: copy d_in[3] (B*N*P = 65536 f32 = 16384 float4) to d_out.
//
// Eleven-round measurement summary:
//   This exact source — ncu: 4.32, 4.13, 4.45, 4.48, 4.45, 4.38 us
//                       harness: 4.58, 4.61, 5.76, 5.63, 5.66 us
//   CE memcpyAsync node: 4.61, 5.89 us (statistically tied, no ncu view)
//   Rejected: 64x256 bounds-checked (6.43), 2 ld/thread @64 CTAs (4.93),
//             __stcs streaming stores (5.41 — .cs evict costs on the
//             harness's d_out re-read).
// Duration = launch/graph-replay floor (T_ovh ~5000 cyc + one DRAM round
// trip); DRAM at 0.8% of peak by construction. Harness variance on identical
// binaries is ~±0.6us — every untried variant's predicted effect is below
// that, so this kernel is final.

__global__ __launch_bounds__(128, 1)
void gcbf_copy_kernel(const float4* __restrict__ src, float4* __restrict__ dst) {
    int i = blockIdx.x * 128 + threadIdx.x;
    dst[i] = src[i];
}

extern "C" void kernel_launch(void* const* d_in, const int* in_sizes, int n_in,
                              void* d_out, int out_size) {
    // inputs: [0] positions, [1] velocities, [2] obstacles, [3] raw_action
    gcbf_copy_kernel<<<128, 128>>>((const float4*)d_in[3], (float4*)d_out);
}